// round 2
// baseline (speedup 1.0000x reference)
#include <cuda_runtime.h>
#include <cuda_bf16.h>
#include <math.h>

// Problem constants
#define Vv 50000
#define Ee 256
#define HD 512
#define Hh 256
#define Bb 64
#define Tt 512
#define Kk 16
#define G4H 1024
#define START_IDX 14
#define STOP_IDX 15
#define NEG (-10000.0f)

// ---------------- device scratch (allocation-free rule: module globals) ----------------
// Recurrent weights, k-major, gate-interleaved: Wr[d][k][j*4+gate]
__device__ float g_Wr[2 * 256 * 1024];
// Precomputed input projections + bias: Gpre[d][t][b][j*4+gate]
__device__ float g_Gpre[2ull * Tt * Bb * G4H];          // 268 MB
// Hidden state history: hs[d][t][b][j]
__device__ float g_hs[2ull * Tt * Bb * Hh];             // 67 MB
// CRF emission features: feats[t][b][k]
__device__ float g_feats[(size_t)Tt * Bb * Kk];

__device__ __forceinline__ float sigf(float x) { return 1.0f / (1.0f + expf(-x)); }

// ---------------- kernel 0: reorder recurrent weights ----------------
// g_Wr[d][k][j*4+gate] = w_hh_d[gate*256 + j][k]
__global__ void prep_whh_kernel(const float* __restrict__ whh_f,
                                const float* __restrict__ whh_b) {
    int idx = blockIdx.x * blockDim.x + threadIdx.x;   // over 2*256*1024
    int c = idx & 1023;
    int k = (idx >> 10) & 255;
    int d = idx >> 18;
    int gate = c & 3;
    int j = c >> 2;
    const float* w = d ? whh_b : whh_f;
    g_Wr[idx] = w[(gate * 256 + j) * 256 + k];
}

// ---------------- kernel 1: embedding gather + input projection SGEMM ----------------
// Gpre[d][t][b][c] = sum_e emb[sent[b][t]][e] * w_ih_d[r(c)][e] + bias_d[r(c)]
// r(c) = (c&3)*256 + (c>>2)    (gate-interleave mapping)
// M = T*B = 32768 (m = t*64+b), N = 1024, K = 256. 128x128 tiles, BK=8, 8x8/thread.
__global__ __launch_bounds__(256) void input_proj_kernel(
    const int*   __restrict__ sentence,
    const float* __restrict__ emb,
    const float* __restrict__ wih_f, const float* __restrict__ bf,
    const float* __restrict__ wih_b, const float* __restrict__ bbias) {
    const int d = blockIdx.z;
    const float* wih = d ? wih_b : wih_f;
    const float* bias = d ? bbias : bf;

    __shared__ float As[8][128];
    __shared__ float Bs[8][128];

    const int tid = threadIdx.x;
    const int tx = tid & 15;
    const int ty = tid >> 4;
    const int m0 = blockIdx.y * 128;
    const int c0 = blockIdx.x * 128;

    // A-load coords (fixed across k-loop)
    const int lr = tid >> 1;           // 0..127
    const int lk = (tid & 1) << 2;     // 0 or 4
    const int mA = m0 + lr;
    const int tA = mA >> 6, bA = mA & 63;
    const int tok = sentence[bA * Tt + tA];
    const float* arow = emb + (size_t)tok * Ee;
    // B-load coords
    const int cl = lr;
    const int cB = c0 + cl;
    const int rB = ((cB & 3) << 8) | (cB >> 2);
    const float* brow = wih + (size_t)rB * Ee;

    float acc[8][8];
#pragma unroll
    for (int i = 0; i < 8; i++)
#pragma unroll
        for (int j = 0; j < 8; j++) acc[i][j] = 0.0f;

    for (int kb = 0; kb < Ee; kb += 8) {
        float4 av = *(const float4*)(arow + kb + lk);
        float4 bv = *(const float4*)(brow + kb + lk);
        As[lk + 0][lr] = av.x; As[lk + 1][lr] = av.y;
        As[lk + 2][lr] = av.z; As[lk + 3][lr] = av.w;
        Bs[lk + 0][cl] = bv.x; Bs[lk + 1][cl] = bv.y;
        Bs[lk + 2][cl] = bv.z; Bs[lk + 3][cl] = bv.w;
        __syncthreads();
#pragma unroll
        for (int kk = 0; kk < 8; kk++) {
            float ra[8], rb[8];
#pragma unroll
            for (int i = 0; i < 8; i++) ra[i] = As[kk][ty * 8 + i];
#pragma unroll
            for (int j = 0; j < 8; j++) rb[j] = Bs[kk][tx * 8 + j];
#pragma unroll
            for (int i = 0; i < 8; i++)
#pragma unroll
                for (int j = 0; j < 8; j++) acc[i][j] += ra[i] * rb[j];
        }
        __syncthreads();
    }

    // bias per output column
    float bsv[8];
#pragma unroll
    for (int j = 0; j < 8; j++) {
        int c = c0 + tx * 8 + j;
        bsv[j] = bias[((c & 3) << 8) | (c >> 2)];
    }
#pragma unroll
    for (int i = 0; i < 8; i++) {
        int m = m0 + ty * 8 + i;
        int t = m >> 6, b = m & 63;
        float* outp = g_Gpre + (((size_t)d * Tt + t) * Bb + b) * G4H + c0 + tx * 8;
#pragma unroll
        for (int j = 0; j < 8; j++) outp[j] = acc[i][j] + bsv[j];
    }
}

// ---------------- kernel 2: LSTM recurrence ----------------
// One block per (direction, batch). 256 threads; thread j owns hidden column j
// (all 4 gates, via the gate-interleaved weight layout -> one LDG.128 per k).
__global__ __launch_bounds__(256) void lstm_rec_kernel() {
    const int j = threadIdx.x;
    const int blk = blockIdx.x;
    const int d = blk >> 6;
    const int b = blk & 63;

    __shared__ float h_sm[2][256];
    h_sm[0][j] = 0.0f;
    float c = 0.0f;
    __syncthreads();

    const float4* Wr4 = ((const float4*)g_Wr) + (size_t)d * 256 * 256;  // [k][256]
    int cur = 0;
    for (int s = 0; s < Tt; s++) {
        const int t = d ? (Tt - 1 - s) : s;
        float4 gp = ((const float4*)g_Gpre)[(((size_t)d * Tt + t) * Bb + b) * 256 + j];
        float a0 = gp.x, a1 = gp.y, a2 = gp.z, a3 = gp.w;
        const float* hc = h_sm[cur];
#pragma unroll 8
        for (int k = 0; k < 256; k++) {
            float hk = hc[k];
            float4 wv = Wr4[k * 256 + j];
            a0 += wv.x * hk; a1 += wv.y * hk;
            a2 += wv.z * hk; a3 += wv.w * hk;
        }
        float ig = sigf(a0), fg = sigf(a1), gg = tanhf(a2), og = sigf(a3);
        c = fg * c + ig * gg;
        float h = og * tanhf(c);
        g_hs[(((size_t)d * Tt + t) * Bb + b) * Hh + j] = h;
        h_sm[cur ^ 1][j] = h;
        __syncthreads();
        cur ^= 1;
    }
}

// ---------------- kernel 3: emission features ----------------
// feats[t][b][k] = [hf|hb] . w_out[k] + b_out[k].  One warp per (t,b) row.
__global__ __launch_bounds__(256) void feats_kernel(const float* __restrict__ w_out,
                                                    const float* __restrict__ b_out) {
    const int lane = threadIdx.x & 31;
    const int warp = threadIdx.x >> 5;
    const int m = blockIdx.x * 8 + warp;       // 0..32767
    const int t = m >> 6, b = m & 63;

    __shared__ float f_sm[8][16];

    float acc[16];
#pragma unroll
    for (int kk = 0; kk < 16; kk++) acc[kk] = 0.0f;

    const float* hf = g_hs + ((size_t)t * Bb + b) * Hh;
    const float* hb = g_hs + ((size_t)Tt * Bb * Hh) + ((size_t)t * Bb + b) * Hh;

#pragma unroll
    for (int i = 0; i < 16; i++) {
        int dd = i * 32 + lane;
        float hv = (dd < Hh) ? hf[dd] : hb[dd - Hh];
#pragma unroll
        for (int kk = 0; kk < 16; kk++) acc[kk] += hv * w_out[kk * HD + dd];
    }
    // warp reduce each of 16 sums to lane 0, stash in smem
#pragma unroll
    for (int kk = 0; kk < 16; kk++) {
        float s = acc[kk];
        s += __shfl_down_sync(0xffffffffu, s, 16);
        s += __shfl_down_sync(0xffffffffu, s, 8);
        s += __shfl_down_sync(0xffffffffu, s, 4);
        s += __shfl_down_sync(0xffffffffu, s, 2);
        s += __shfl_down_sync(0xffffffffu, s, 1);
        if (lane == 0) f_sm[warp][kk] = s;
    }
    __syncwarp();
    if (lane < 16)
        g_feats[((size_t)t * Bb + b) * Kk + lane] = f_sm[warp][lane] + b_out[lane];
}

// ---------------- kernel 4: Viterbi forward + backtrace ----------------
// One warp (block of 32) per batch. Backpointers kept in SMEM (uint8).
__global__ __launch_bounds__(32) void viterbi_kernel(const float* __restrict__ trans,
                                                     float* __restrict__ out) {
    const int b = blockIdx.x;
    const int lane = threadIdx.x;

    __shared__ unsigned char bp_sm[Tt][16];

    float trans_r[16];
#pragma unroll
    for (int p = 0; p < 16; p++)
        trans_r[p] = (lane < 16) ? trans[lane * 16 + p] : 0.0f;

    float fv = (lane == START_IDX) ? 0.0f : NEG;
    if (lane >= 16) fv = NEG;

    for (int t = 0; t < Tt; t++) {
        float feat = (lane < 16) ? g_feats[((size_t)t * Bb + b) * Kk + lane] : 0.0f;
        float m = -3.4e38f;
        int am = 0;
#pragma unroll
        for (int p = 0; p < 16; p++) {
            float v = __shfl_sync(0xffffffffu, fv, p) + trans_r[p];
            if (v > m) { m = v; am = p; }
        }
        float nfv = m + feat;
        fv = (lane < 16) ? nfv : NEG;
        if (lane < 16) bp_sm[t][lane] = (unsigned char)am;
    }
    __syncwarp();

    // terminal: fv + trans[STOP][prev]; argmax (first occurrence)
    float best = -3.4e38f;
    int bt = 0;
#pragma unroll
    for (int s = 0; s < 16; s++) {
        float v = __shfl_sync(0xffffffffu, fv, s);
        float tv = v + trans[STOP_IDX * 16 + s];
        if (tv > best) { best = tv; bt = s; }
    }
    if (lane == 0) {
        out[b] = best;
        int tag = bt;
        for (int t = Tt - 1; t >= 0; t--) {
            out[64 + (size_t)t * Bb + b] = (float)tag;
            tag = bp_sm[t][tag];
        }
    }
}

// ---------------- launcher ----------------
extern "C" void kernel_launch(void* const* d_in, const int* in_sizes, int n_in,
                              void* d_out, int out_size) {
    const int*   sentence = (const int*)d_in[0];
    const float* emb      = (const float*)d_in[1];
    const float* w_ih_f   = (const float*)d_in[2];
    const float* w_hh_f   = (const float*)d_in[3];
    const float* b_f      = (const float*)d_in[4];
    const float* w_ih_b   = (const float*)d_in[5];
    const float* w_hh_b   = (const float*)d_in[6];
    const float* b_b      = (const float*)d_in[7];
    const float* w_out    = (const float*)d_in[8];
    const float* b_out    = (const float*)d_in[9];
    const float* trans    = (const float*)d_in[10];
    float* out = (float*)d_out;
    (void)in_sizes; (void)n_in; (void)out_size;

    // 0. weight reorder
    prep_whh_kernel<<<2048, 256>>>(w_hh_f, w_hh_b);
    // 1. embedding gather + input projection (both directions)
    dim3 pg(G4H / 128, (Tt * Bb) / 128, 2);
    input_proj_kernel<<<pg, 256>>>(sentence, emb, w_ih_f, b_f, w_ih_b, b_b);
    // 2. recurrence: 128 persistent blocks, one per (dir, batch)
    lstm_rec_kernel<<<128, 256>>>();
    // 3. emission features
    feats_kernel<<<(Tt * Bb) / 8, 256>>>(w_out, b_out);
    // 4. viterbi
    viterbi_kernel<<<Bb, 32>>>(trans, out);
}

// round 3
// speedup vs baseline: 3.1571x; 3.1571x over previous
#include <cuda_runtime.h>
#include <cuda_bf16.h>
#include <math.h>
#include <stdint.h>

// Problem constants
#define Vv 50000
#define Ee 256
#define HD 512
#define Hh 256
#define Bb 64
#define Tt 512
#define Kk 16
#define G4H 1024
#define START_IDX 14
#define STOP_IDX 15
#define NEG (-10000.0f)

// ---------------- device scratch ----------------
// Recurrent weights, col-major over k: g_Wr2[d][col][k], col = j*4 + gate
__device__ __align__(16) float g_Wr2[2 * 1024 * 256];
// Input projections + bias: Gpre[d][t][b][j*4+gate]
__device__ __align__(16) float g_Gpre[2ull * Tt * Bb * G4H];     // 268 MB
// Hidden state history: hs[d][t][b][j]
__device__ __align__(16) float g_hs[2ull * Tt * Bb * Hh];        // 67 MB
// CRF emission features
__device__ float g_feats[(size_t)Tt * Bb * Kk];

// ---------------- f32x2 helpers (Blackwell packed fp32) ----------------
__device__ __forceinline__ void ffma2(unsigned long long& d,
                                      unsigned long long a, unsigned long long b) {
    asm("fma.rn.f32x2 %0, %1, %2, %0;" : "+l"(d) : "l"(a), "l"(b));
}
__device__ __forceinline__ unsigned long long pack2(float x, float y) {
    unsigned long long r;
    asm("mov.b64 %0, {%1, %2};" : "=l"(r) : "f"(x), "f"(y));
    return r;
}
__device__ __forceinline__ float hadd2(unsigned long long v) {
    float lo = __uint_as_float((unsigned)(v & 0xffffffffull));
    float hi = __uint_as_float((unsigned)(v >> 32));
    return lo + hi;
}

__device__ __forceinline__ float fsig(float x) {
    return __fdividef(1.0f, 1.0f + __expf(-x));
}
__device__ __forceinline__ float ftanh(float x) {
    return __fdividef(2.0f, 1.0f + __expf(-2.0f * x)) - 1.0f;
}

__device__ __forceinline__ void st_cluster_f32(uint32_t addr, uint32_t rank, float v) {
    uint32_t r;
    asm volatile("mapa.shared::cluster.u32 %0, %1, %2;" : "=r"(r) : "r"(addr), "r"(rank));
    asm volatile("st.shared::cluster.f32 [%0], %1;" :: "r"(r), "f"(v) : "memory");
}

// ---------------- kernel 0: reorder recurrent weights ----------------
// g_Wr2[d][col][k] = w_hh_d[gate*256 + j][k],  col = j*4 + gate
__global__ void prep_whh_kernel(const float* __restrict__ whh_f,
                                const float* __restrict__ whh_b) {
    int idx = blockIdx.x * blockDim.x + threadIdx.x;   // over 2*1024*256
    int k = idx & 255;
    int col = (idx >> 8) & 1023;
    int d = idx >> 18;
    int gate = col & 3;
    int j = col >> 2;
    const float* w = d ? whh_b : whh_f;
    g_Wr2[idx] = w[(gate * 256 + j) * 256 + k];
}

// ---------------- kernel 1: embedding gather + input projection SGEMM ----------------
// Gpre[d][t][b][c] = sum_e emb[sent[b][t]][e] * w_ih_d[r(c)][e] + bias_d[r(c)]
// r(c) = (c&3)*256 + (c>>2).  M=32768, N=1024, K=256; 128x128 tiles, BK=8.
// Inner product uses packed f32x2 FFMA (j-pair packing).
__global__ __launch_bounds__(256) void input_proj_kernel(
    const int*   __restrict__ sentence,
    const float* __restrict__ emb,
    const float* __restrict__ wih_f, const float* __restrict__ bf,
    const float* __restrict__ wih_b, const float* __restrict__ bbias) {
    const int d = blockIdx.z;
    const float* wih = d ? wih_b : wih_f;
    const float* bias = d ? bbias : bf;

    __shared__ __align__(16) float As[8][128];
    __shared__ __align__(16) float Bs[8][128];

    const int tid = threadIdx.x;
    const int tx = tid & 15;
    const int ty = tid >> 4;
    const int m0 = blockIdx.y * 128;
    const int c0 = blockIdx.x * 128;

    const int lr = tid >> 1;
    const int lk = (tid & 1) << 2;
    const int mA = m0 + lr;
    const int tA = mA >> 6, bA = mA & 63;
    const int tok = sentence[bA * Tt + tA];
    const float* arow = emb + (size_t)tok * Ee;
    const int cB = c0 + lr;
    const int rB = ((cB & 3) << 8) | (cB >> 2);
    const float* brow = wih + (size_t)rB * Ee;

    unsigned long long acc2[8][4];
#pragma unroll
    for (int i = 0; i < 8; i++)
#pragma unroll
        for (int j = 0; j < 4; j++) acc2[i][j] = 0ull;

    for (int kb = 0; kb < Ee; kb += 8) {
        float4 av = *(const float4*)(arow + kb + lk);
        float4 bv = *(const float4*)(brow + kb + lk);
        As[lk + 0][lr] = av.x; As[lk + 1][lr] = av.y;
        As[lk + 2][lr] = av.z; As[lk + 3][lr] = av.w;
        Bs[lk + 0][lr] = bv.x; Bs[lk + 1][lr] = bv.y;
        Bs[lk + 2][lr] = bv.z; Bs[lk + 3][lr] = bv.w;
        __syncthreads();
#pragma unroll
        for (int kk = 0; kk < 8; kk++) {
            float4 ra0 = *(const float4*)&As[kk][ty * 8];
            float4 ra1 = *(const float4*)&As[kk][ty * 8 + 4];
            ulonglong2 rb0 = *(const ulonglong2*)&Bs[kk][tx * 8];
            ulonglong2 rb1 = *(const ulonglong2*)&Bs[kk][tx * 8 + 4];
            unsigned long long rb2[4] = {rb0.x, rb0.y, rb1.x, rb1.y};
            float ra[8] = {ra0.x, ra0.y, ra0.z, ra0.w, ra1.x, ra1.y, ra1.z, ra1.w};
#pragma unroll
            for (int i = 0; i < 8; i++) {
                unsigned long long ra2 = pack2(ra[i], ra[i]);
#pragma unroll
                for (int j = 0; j < 4; j++) ffma2(acc2[i][j], ra2, rb2[j]);
            }
        }
        __syncthreads();
    }

    float bsv[8];
#pragma unroll
    for (int j = 0; j < 8; j++) {
        int c = c0 + tx * 8 + j;
        bsv[j] = bias[((c & 3) << 8) | (c >> 2)];
    }
#pragma unroll
    for (int i = 0; i < 8; i++) {
        int m = m0 + ty * 8 + i;
        int t = m >> 6, b = m & 63;
        float* outp = g_Gpre + (((size_t)d * Tt + t) * Bb + b) * G4H + c0 + tx * 8;
#pragma unroll
        for (int j = 0; j < 4; j++) {
            unsigned long long v = acc2[i][j];
            outp[2 * j + 0] = __uint_as_float((unsigned)(v & 0xffffffffull)) + bsv[2 * j + 0];
            outp[2 * j + 1] = __uint_as_float((unsigned)(v >> 32)) + bsv[2 * j + 1];
        }
    }
}

// ---------------- kernel 2: LSTM recurrence (cluster, register-resident weights) ----
// Grid: 128 CTAs, cluster size 8. Cluster cid = blockIdx.x>>3 handles direction
// d = cid>>3, batch group bg = cid&7 (batches bg*8..bg*8+7). CTA rank r owns gate
// columns [r*128, r*128+128) = j in [r*32, r*32+32).
// Thread t: j_local = t>>3, kq = t&7 (k-range [kq*32, kq*32+32)).
// Weights (4 gates x 32 k) live in 128 registers as f32x2 pairs. h in SMEM
// (stride 260 floats -> conflict-free). Reduce-scatter over 8 kq lanes with
// slot = b XOR kq. One cluster barrier per step.
__global__ void __cluster_dims__(8, 1, 1) __launch_bounds__(256, 1) lstm_rec_kernel() {
    const int tidx = threadIdx.x;
    const int kq = tidx & 7;
    const int jl = tidx >> 3;
    const int cid = blockIdx.x >> 3;
    const int r = blockIdx.x & 7;
    const int d = cid >> 3;
    const int bg = cid & 7;
    const int b = bg * 8 + kq;
    const int jglob = r * 32 + jl;
    const int col0 = jglob * 4;

    __shared__ __align__(16) float h_sm[2][8][260];

    // ---- load weight slice into registers: wu[g][i2], i2 covers k-pairs ----
    unsigned long long wu[4][16];
    const float* wbase = g_Wr2 + (size_t)d * 1024 * 256;
#pragma unroll
    for (int g = 0; g < 4; g++) {
        const ulonglong2* p = (const ulonglong2*)(wbase + (size_t)(col0 + g) * 256 + kq * 32);
#pragma unroll
        for (int q = 0; q < 8; q++) {
            ulonglong2 v = p[q];
            wu[g][2 * q + 0] = v.x;
            wu[g][2 * q + 1] = v.y;
        }
    }

    // zero current h buffer
    for (int i = tidx; i < 8 * 260; i += 256) ((float*)h_sm[0])[i] = 0.0f;
    float c = 0.0f;
    __syncthreads();

    uint32_t smem_u32;
    {
        asm("{ .reg .u64 t0; cvta.to.shared.u64 t0, %1; cvt.u32.u64 %0, t0; }"
            : "=r"(smem_u32) : "l"((void*)h_sm));
    }

    const int t0 = d ? (Tt - 1) : 0;
    const int tstep = d ? -1 : 1;
    const float4* gpre4 = (const float4*)g_Gpre;

    // prefetch Gpre for step 0
    float4 g4 = gpre4[(((size_t)d * Tt + t0) * Bb + b) * 256 + jglob];

    int cur = 0;
    for (int s = 0; s < Tt; s++) {
        const int t = t0 + s * tstep;

        // ---- GEMM: accf[g][slot], slot = b_local ^ kq ----
        float accf[4][8];
#pragma unroll
        for (int sl = 0; sl < 8; sl++) {
            unsigned long long a2[4] = {0ull, 0ull, 0ull, 0ull};
            const ulonglong2* hp = (const ulonglong2*)&h_sm[cur][sl ^ kq][kq * 32];
#pragma unroll
            for (int i = 0; i < 8; i++) {
                ulonglong2 h4 = hp[i];
                ffma2(a2[0], wu[0][2 * i], h4.x); ffma2(a2[0], wu[0][2 * i + 1], h4.y);
                ffma2(a2[1], wu[1][2 * i], h4.x); ffma2(a2[1], wu[1][2 * i + 1], h4.y);
                ffma2(a2[2], wu[2][2 * i], h4.x); ffma2(a2[2], wu[2][2 * i + 1], h4.y);
                ffma2(a2[3], wu[3][2 * i], h4.x); ffma2(a2[3], wu[3][2 * i + 1], h4.y);
            }
#pragma unroll
            for (int g = 0; g < 4; g++) accf[g][sl] = hadd2(a2[g]);
        }

        // prefetch next step's Gpre (independent of this step)
        float4 g4n = g4;
        if (s + 1 < Tt) {
            const int tn = t + tstep;
            g4n = gpre4[(((size_t)d * Tt + tn) * Bb + b) * 256 + jglob];
        }

        // ---- reduce-scatter over kq lanes: accf[g][0] = full sum for b_local=kq ----
#pragma unroll
        for (int g = 0; g < 4; g++) {
            accf[g][0] += __shfl_xor_sync(0xffffffffu, accf[g][4], 4);
            accf[g][1] += __shfl_xor_sync(0xffffffffu, accf[g][5], 4);
            accf[g][2] += __shfl_xor_sync(0xffffffffu, accf[g][6], 4);
            accf[g][3] += __shfl_xor_sync(0xffffffffu, accf[g][7], 4);
            accf[g][0] += __shfl_xor_sync(0xffffffffu, accf[g][2], 2);
            accf[g][1] += __shfl_xor_sync(0xffffffffu, accf[g][3], 2);
            accf[g][0] += __shfl_xor_sync(0xffffffffu, accf[g][1], 1);
        }

        // ---- LSTM cell for (j = jglob, batch = b) ----
        float a0 = accf[0][0] + g4.x;
        float a1 = accf[1][0] + g4.y;
        float a2v = accf[2][0] + g4.z;
        float a3 = accf[3][0] + g4.w;
        float ig = fsig(a0), fg = fsig(a1), gv = ftanh(a2v), og = fsig(a3);
        c = fg * c + ig * gv;
        float h = og * ftanh(c);

        // hidden-state history for feats
        g_hs[(((size_t)d * Tt + t) * Bb + b) * Hh + jglob] = h;

        // broadcast h to all 8 CTAs' next buffer (incl. self)
        uint32_t dst = smem_u32 + (uint32_t)(((cur ^ 1) * 8 * 260 + kq * 260 + jglob) * 4);
#pragma unroll
        for (int rk = 0; rk < 8; rk++) st_cluster_f32(dst, rk, h);

        asm volatile("barrier.cluster.arrive.aligned;" ::: "memory");
        g4 = g4n;
        asm volatile("barrier.cluster.wait.aligned;" ::: "memory");
        cur ^= 1;
    }
}

// ---------------- kernel 3: emission features ----------------
__global__ __launch_bounds__(256) void feats_kernel(const float* __restrict__ w_out,
                                                    const float* __restrict__ b_out) {
    const int lane = threadIdx.x & 31;
    const int warp = threadIdx.x >> 5;
    const int m = blockIdx.x * 8 + warp;
    const int t = m >> 6, b = m & 63;

    __shared__ float f_sm[8][16];

    float acc[16];
#pragma unroll
    for (int kk = 0; kk < 16; kk++) acc[kk] = 0.0f;

    const float* hf = g_hs + ((size_t)t * Bb + b) * Hh;
    const float* hb = g_hs + ((size_t)Tt * Bb * Hh) + ((size_t)t * Bb + b) * Hh;

#pragma unroll
    for (int i = 0; i < 16; i++) {
        int dd = i * 32 + lane;
        float hv = (dd < Hh) ? hf[dd] : hb[dd - Hh];
#pragma unroll
        for (int kk = 0; kk < 16; kk++) acc[kk] += hv * w_out[kk * HD + dd];
    }
#pragma unroll
    for (int kk = 0; kk < 16; kk++) {
        float s = acc[kk];
        s += __shfl_down_sync(0xffffffffu, s, 16);
        s += __shfl_down_sync(0xffffffffu, s, 8);
        s += __shfl_down_sync(0xffffffffu, s, 4);
        s += __shfl_down_sync(0xffffffffu, s, 2);
        s += __shfl_down_sync(0xffffffffu, s, 1);
        if (lane == 0) f_sm[warp][kk] = s;
    }
    __syncwarp();
    if (lane < 16)
        g_feats[((size_t)t * Bb + b) * Kk + lane] = f_sm[warp][lane] + b_out[lane];
}

// ---------------- kernel 4: Viterbi forward + backtrace ----------------
__global__ __launch_bounds__(32) void viterbi_kernel(const float* __restrict__ trans,
                                                     float* __restrict__ out) {
    const int b = blockIdx.x;
    const int lane = threadIdx.x;

    __shared__ unsigned char bp_sm[Tt][16];

    float trans_r[16];
#pragma unroll
    for (int p = 0; p < 16; p++)
        trans_r[p] = (lane < 16) ? trans[lane * 16 + p] : 0.0f;

    float fv = (lane == START_IDX) ? 0.0f : NEG;
    if (lane >= 16) fv = NEG;

    for (int t = 0; t < Tt; t++) {
        float feat = (lane < 16) ? g_feats[((size_t)t * Bb + b) * Kk + lane] : 0.0f;
        float m = -3.4e38f;
        int am = 0;
#pragma unroll
        for (int p = 0; p < 16; p++) {
            float v = __shfl_sync(0xffffffffu, fv, p) + trans_r[p];
            if (v > m) { m = v; am = p; }
        }
        float nfv = m + feat;
        fv = (lane < 16) ? nfv : NEG;
        if (lane < 16) bp_sm[t][lane] = (unsigned char)am;
    }
    __syncwarp();

    float best = -3.4e38f;
    int bt = 0;
#pragma unroll
    for (int s = 0; s < 16; s++) {
        float v = __shfl_sync(0xffffffffu, fv, s);
        float tv = v + trans[STOP_IDX * 16 + s];
        if (tv > best) { best = tv; bt = s; }
    }
    if (lane == 0) {
        out[b] = best;
        int tag = bt;
        for (int t = Tt - 1; t >= 0; t--) {
            out[64 + (size_t)t * Bb + b] = (float)tag;
            tag = bp_sm[t][tag];
        }
    }
}

// ---------------- launcher ----------------
extern "C" void kernel_launch(void* const* d_in, const int* in_sizes, int n_in,
                              void* d_out, int out_size) {
    const int*   sentence = (const int*)d_in[0];
    const float* emb      = (const float*)d_in[1];
    const float* w_ih_f   = (const float*)d_in[2];
    const float* w_hh_f   = (const float*)d_in[3];
    const float* b_f      = (const float*)d_in[4];
    const float* w_ih_b   = (const float*)d_in[5];
    const float* w_hh_b   = (const float*)d_in[6];
    const float* b_b      = (const float*)d_in[7];
    const float* w_out    = (const float*)d_in[8];
    const float* b_out    = (const float*)d_in[9];
    const float* trans    = (const float*)d_in[10];
    float* out = (float*)d_out;
    (void)in_sizes; (void)n_in; (void)out_size;

    prep_whh_kernel<<<2048, 256>>>(w_hh_f, w_hh_b);
    dim3 pg(G4H / 128, (Tt * Bb) / 128, 2);
    input_proj_kernel<<<pg, 256>>>(sentence, emb, w_ih_f, b_f, w_ih_b, b_b);
    lstm_rec_kernel<<<128, 256>>>();
    feats_kernel<<<(Tt * Bb) / 8, 256>>>(w_out, b_out);
    viterbi_kernel<<<Bb, 32>>>(trans, out);
}

// round 4
// speedup vs baseline: 3.5307x; 1.1183x over previous
#include <cuda_runtime.h>
#include <cuda_bf16.h>
#include <math.h>
#include <stdint.h>

// Problem constants
#define Vv 50000
#define Ee 256
#define HD 512
#define Hh 256
#define Bb 64
#define Tt 512
#define Kk 16
#define G4H 1024
#define START_IDX 14
#define STOP_IDX 15
#define NEG (-10000.0f)

// ---------------- device scratch ----------------
__device__ __align__(16) float g_Wr2[2 * 1024 * 256];               // [d][col][k], col=j*4+gate
__device__ __align__(16) float g_Gpre[2ull * Tt * Bb * G4H];        // 268 MB
__device__ __align__(16) float g_hs[2ull * Tt * Bb * Hh];           // 67 MB
__device__ float g_feats[(size_t)Tt * Bb * Kk];

// ---------------- f32x2 helpers ----------------
__device__ __forceinline__ void ffma2(unsigned long long& d,
                                      unsigned long long a, unsigned long long b) {
    asm("fma.rn.f32x2 %0, %1, %2, %0;" : "+l"(d) : "l"(a), "l"(b));
}
__device__ __forceinline__ float hadd2(unsigned long long v) {
    float lo = __uint_as_float((unsigned)(v & 0xffffffffull));
    float hi = __uint_as_float((unsigned)(v >> 32));
    return lo + hi;
}
__device__ __forceinline__ float fsig(float x) {
    return __fdividef(1.0f, 1.0f + __expf(-x));
}
__device__ __forceinline__ float ftanh(float x) {
    return __fdividef(2.0f, 1.0f + __expf(-2.0f * x)) - 1.0f;
}

// ---------------- cluster mbarrier helpers ----------------
__device__ __forceinline__ uint32_t smem_u32_of(const void* p) {
    uint32_t a;
    asm("{ .reg .u64 t0; cvta.to.shared.u64 t0, %1; cvt.u32.u64 %0, t0; }"
        : "=r"(a) : "l"(p));
    return a;
}
__device__ __forceinline__ void mbar_init(uint32_t mbar, uint32_t cnt) {
    asm volatile("mbarrier.init.shared.b64 [%0], %1;" :: "r"(mbar), "r"(cnt) : "memory");
}
__device__ __forceinline__ void mbar_arrive_expect(uint32_t mbar, uint32_t tx) {
    asm volatile("mbarrier.arrive.expect_tx.shared.b64 _, [%0], %1;"
                 :: "r"(mbar), "r"(tx) : "memory");
}
__device__ __forceinline__ void mbar_wait_cluster(uint32_t mbar, uint32_t parity) {
    asm volatile(
        "{\n\t"
        ".reg .pred P1;\n\t"
        "WAIT_%=:\n\t"
        "mbarrier.try_wait.parity.acquire.cluster.shared::cta.b64 P1, [%0], %1, 0x989680;\n\t"
        "@P1 bra.uni DONE_%=;\n\t"
        "bra.uni WAIT_%=;\n\t"
        "DONE_%=:\n\t"
        "}"
        :: "r"(mbar), "r"(parity) : "memory");
}
__device__ __forceinline__ uint32_t mapa_u32(uint32_t addr, uint32_t rank) {
    uint32_t r;
    asm("mapa.shared::cluster.u32 %0, %1, %2;" : "=r"(r) : "r"(addr), "r"(rank));
    return r;
}
__device__ __forceinline__ void st_async_f32(uint32_t daddr, uint32_t val, uint32_t mbar) {
    asm volatile(
        "st.async.weak.shared::cluster.mbarrier::complete_tx::bytes.b32 [%0], %1, [%2];"
        :: "r"(daddr), "r"(val), "r"(mbar) : "memory");
}

// ---------------- kernel 0: reorder recurrent weights ----------------
__global__ void prep_whh_kernel(const float* __restrict__ whh_f,
                                const float* __restrict__ whh_b) {
    int idx = blockIdx.x * blockDim.x + threadIdx.x;   // over 2*1024*256
    int k = idx & 255;
    int col = (idx >> 8) & 1023;
    int d = idx >> 18;
    int gate = col & 3;
    int j = col >> 2;
    const float* w = d ? whh_b : whh_f;
    g_Wr2[idx] = w[(gate * 256 + j) * 256 + k];
}

// ---------------- kernel 1: embedding gather + input projection SGEMM ----------------
// Double-buffered smem, duplicated-A layout (FFMA2 operands direct from LDS.128),
// one __syncthreads per k-slab, prefetched LDGs.
__global__ __launch_bounds__(256, 2) void input_proj_kernel(
    const int*   __restrict__ sentence,
    const float* __restrict__ emb,
    const float* __restrict__ wih_f, const float* __restrict__ bf,
    const float* __restrict__ wih_b, const float* __restrict__ bbias) {
    const int d = blockIdx.z;
    const float* wih = d ? wih_b : wih_f;
    const float* bias = d ? bbias : bf;

    __shared__ __align__(16) float As2[2][8][256];   // duplicated: [2m]=[2m+1]=a_m
    __shared__ __align__(16) float Bs[2][8][128];

    const int tid = threadIdx.x;
    const int tx = tid & 15;
    const int ty = tid >> 4;
    const int m0 = blockIdx.y * 128;
    const int c0 = blockIdx.x * 128;

    const int lr = tid >> 1;           // 0..127
    const int lk = (tid & 1) << 2;     // 0 or 4
    const int mA = m0 + lr;
    const int tA = mA >> 6, bA = mA & 63;
    const int tok = sentence[bA * Tt + tA];
    const float* arow = emb + (size_t)tok * Ee;
    const int cB = c0 + lr;
    const int rB = ((cB & 3) << 8) | (cB >> 2);
    const float* brow = wih + (size_t)rB * Ee;

    unsigned long long acc2[8][4];
#pragma unroll
    for (int i = 0; i < 8; i++)
#pragma unroll
        for (int j = 0; j < 4; j++) acc2[i][j] = 0ull;

    // prologue: fill buffer 0
    {
        float4 av = *(const float4*)(arow + lk);
        float4 bv = *(const float4*)(brow + lk);
        float avv[4] = {av.x, av.y, av.z, av.w};
        float bvv[4] = {bv.x, bv.y, bv.z, bv.w};
#pragma unroll
        for (int i = 0; i < 4; i++) {
            *(float2*)&As2[0][lk + i][2 * lr] = make_float2(avv[i], avv[i]);
            Bs[0][lk + i][lr] = bvv[i];
        }
    }
    __syncthreads();

    for (int it = 0; it < 32; it++) {
        const int cur = it & 1;
        float4 avn, bvn;
        if (it < 31) {
            avn = *(const float4*)(arow + (it + 1) * 8 + lk);
            bvn = *(const float4*)(brow + (it + 1) * 8 + lk);
        }
#pragma unroll
        for (int kk = 0; kk < 8; kk++) {
            const ulonglong2* pa = (const ulonglong2*)&As2[cur][kk][ty * 16];
            ulonglong2 a01 = pa[0], a23 = pa[1], a45 = pa[2], a67 = pa[3];
            unsigned long long ra2[8] = {a01.x, a01.y, a23.x, a23.y,
                                         a45.x, a45.y, a67.x, a67.y};
            const ulonglong2* pb = (const ulonglong2*)&Bs[cur][kk][tx * 8];
            ulonglong2 b01 = pb[0], b23 = pb[1];
            unsigned long long rb2[4] = {b01.x, b01.y, b23.x, b23.y};
#pragma unroll
            for (int i = 0; i < 8; i++)
#pragma unroll
                for (int j = 0; j < 4; j++) ffma2(acc2[i][j], ra2[i], rb2[j]);
        }
        if (it < 31) {
            const int nxt = cur ^ 1;
            float avv[4] = {avn.x, avn.y, avn.z, avn.w};
            float bvv[4] = {bvn.x, bvn.y, bvn.z, bvn.w};
#pragma unroll
            for (int i = 0; i < 4; i++) {
                *(float2*)&As2[nxt][lk + i][2 * lr] = make_float2(avv[i], avv[i]);
                Bs[nxt][lk + i][lr] = bvv[i];
            }
        }
        __syncthreads();
    }

    float bsv[8];
#pragma unroll
    for (int j = 0; j < 8; j++) {
        int c = c0 + tx * 8 + j;
        bsv[j] = bias[((c & 3) << 8) | (c >> 2)];
    }
#pragma unroll
    for (int i = 0; i < 8; i++) {
        int m = m0 + ty * 8 + i;
        int t = m >> 6, b = m & 63;
        float* outp = g_Gpre + (((size_t)d * Tt + t) * Bb + b) * G4H + c0 + tx * 8;
        float4 o0, o1;
        o0.x = __uint_as_float((unsigned)(acc2[i][0] & 0xffffffffull)) + bsv[0];
        o0.y = __uint_as_float((unsigned)(acc2[i][0] >> 32)) + bsv[1];
        o0.z = __uint_as_float((unsigned)(acc2[i][1] & 0xffffffffull)) + bsv[2];
        o0.w = __uint_as_float((unsigned)(acc2[i][1] >> 32)) + bsv[3];
        o1.x = __uint_as_float((unsigned)(acc2[i][2] & 0xffffffffull)) + bsv[4];
        o1.y = __uint_as_float((unsigned)(acc2[i][2] >> 32)) + bsv[5];
        o1.z = __uint_as_float((unsigned)(acc2[i][3] & 0xffffffffull)) + bsv[6];
        o1.w = __uint_as_float((unsigned)(acc2[i][3] >> 32)) + bsv[7];
        *(float4*)(outp) = o0;
        *(float4*)(outp + 4) = o1;
    }
}

// ---------------- kernel 2: LSTM recurrence (cluster, mbarrier/st.async sync) ----
// 128 CTAs, cluster 8. cid=blk>>3: d=cid>>3, batch group bg=cid&7 (8 batches).
// CTA rank r owns j in [r*32, r*32+32). Thread: jl=t>>3, kq=t&7 (k-split 8-way).
// Weights in 128 registers. h broadcast via st.async to all peers' smem; per-step
// sync = transaction-counted mbarrier (8192 bytes = 2048 h values), no BAR at all.
__global__ void __cluster_dims__(8, 1, 1) __launch_bounds__(256, 1) lstm_rec_kernel() {
    const int tidx = threadIdx.x;
    const int kq = tidx & 7;
    const int jl = tidx >> 3;
    const int cid = blockIdx.x >> 3;
    const int r = blockIdx.x & 7;
    const int d = cid >> 3;
    const int bg = cid & 7;
    const int b = bg * 8 + kq;
    const int jglob = r * 32 + jl;
    const int col0 = jglob * 4;

    __shared__ __align__(16) float h_sm[2][8][260];
    __shared__ __align__(8) unsigned long long mbars[2];

    // ---- weights into registers ----
    unsigned long long wu[4][16];
    const float* wbase = g_Wr2 + (size_t)d * 1024 * 256;
#pragma unroll
    for (int g = 0; g < 4; g++) {
        const ulonglong2* p = (const ulonglong2*)(wbase + (size_t)(col0 + g) * 256 + kq * 32);
#pragma unroll
        for (int q = 0; q < 8; q++) {
            ulonglong2 v = p[q];
            wu[g][2 * q + 0] = v.x;
            wu[g][2 * q + 1] = v.y;
        }
    }

    // zero step-0 buffer
    for (int i = tidx; i < 8 * 260; i += 256) ((float*)h_sm[0])[i] = 0.0f;
    float c = 0.0f;

    const uint32_t h_base = smem_u32_of(h_sm);
    const uint32_t mb_base = smem_u32_of(mbars);
    const uint32_t dmb = mb_base - h_base;

    if (tidx == 0) {
        mbar_init(mb_base, 1);
        mbar_init(mb_base + 8, 1);
        // arm phase 0 of both (step 1 data -> mbar[1], step 2 data -> mbar[0])
        mbar_arrive_expect(mb_base, 8192);
        mbar_arrive_expect(mb_base + 8, 8192);
    }
    __syncthreads();
    asm volatile("barrier.cluster.arrive.aligned;" ::: "memory");
    asm volatile("barrier.cluster.wait.aligned;" ::: "memory");

    // mapped peer smem bases
    uint32_t ph[8];
#pragma unroll
    for (int rk = 0; rk < 8; rk++) ph[rk] = mapa_u32(h_base, rk);

    const uint32_t hoff0 = (uint32_t)((kq * 260 + jglob) * 4);
    const uint32_t hoff1 = (uint32_t)(8 * 260 * 4) + hoff0;

    const int t0 = d ? (Tt - 1) : 0;
    const int tstep = d ? -1 : 1;
    const float4* gpre4 = (const float4*)g_Gpre;

    float4 g4 = gpre4[(((size_t)d * Tt + t0) * Bb + b) * 256 + jglob];

    for (int s = 0; s < Tt; s++) {
        const int t = t0 + s * tstep;
        const int cur = s & 1;

        if (s > 0) {
            uint32_t mb = mb_base + (uint32_t)(cur * 8);
            mbar_wait_cluster(mb, ((s - 1) >> 1) & 1);
            if (tidx == 0) mbar_arrive_expect(mb, 8192);   // re-arm for step s+2
        }

        // ---- GEMM: accf[g][slot], slot row = slot ^ kq ----
        float accf[4][8];
#pragma unroll
        for (int sl = 0; sl < 8; sl++) {
            unsigned long long a2[4] = {0ull, 0ull, 0ull, 0ull};
            const ulonglong2* hp = (const ulonglong2*)&h_sm[cur][sl ^ kq][kq * 32];
#pragma unroll
            for (int i = 0; i < 8; i++) {
                ulonglong2 h4 = hp[i];
                ffma2(a2[0], wu[0][2 * i], h4.x); ffma2(a2[0], wu[0][2 * i + 1], h4.y);
                ffma2(a2[1], wu[1][2 * i], h4.x); ffma2(a2[1], wu[1][2 * i + 1], h4.y);
                ffma2(a2[2], wu[2][2 * i], h4.x); ffma2(a2[2], wu[2][2 * i + 1], h4.y);
                ffma2(a2[3], wu[3][2 * i], h4.x); ffma2(a2[3], wu[3][2 * i + 1], h4.y);
            }
#pragma unroll
            for (int g = 0; g < 4; g++) accf[g][sl] = hadd2(a2[g]);
        }

        // prefetch next step's Gpre
        float4 g4n = g4;
        if (s + 1 < Tt) {
            const int tn = t + tstep;
            g4n = gpre4[(((size_t)d * Tt + tn) * Bb + b) * 256 + jglob];
        }

        // ---- reduce-scatter over kq lanes ----
#pragma unroll
        for (int g = 0; g < 4; g++) {
            accf[g][0] += __shfl_xor_sync(0xffffffffu, accf[g][4], 4);
            accf[g][1] += __shfl_xor_sync(0xffffffffu, accf[g][5], 4);
            accf[g][2] += __shfl_xor_sync(0xffffffffu, accf[g][6], 4);
            accf[g][3] += __shfl_xor_sync(0xffffffffu, accf[g][7], 4);
            accf[g][0] += __shfl_xor_sync(0xffffffffu, accf[g][2], 2);
            accf[g][1] += __shfl_xor_sync(0xffffffffu, accf[g][3], 2);
            accf[g][0] += __shfl_xor_sync(0xffffffffu, accf[g][1], 1);
        }

        // ---- LSTM cell ----
        float a0 = accf[0][0] + g4.x;
        float a1 = accf[1][0] + g4.y;
        float a2v = accf[2][0] + g4.z;
        float a3 = accf[3][0] + g4.w;
        float ig = fsig(a0), fg = fsig(a1), gv = ftanh(a2v), og = fsig(a3);
        c = fg * c + ig * gv;
        float h = og * ftanh(c);

        g_hs[(((size_t)d * Tt + t) * Bb + b) * Hh + jglob] = h;

        if (s + 1 < Tt) {
            const uint32_t doff = (cur ^ 1) ? hoff1 : hoff0;
            const uint32_t moff = dmb + (uint32_t)((cur ^ 1) * 8);
            const uint32_t hv = __float_as_uint(h);
#pragma unroll
            for (int rk = 0; rk < 8; rk++)
                st_async_f32(ph[rk] + doff, hv, ph[rk] + moff);
        }
        g4 = g4n;
    }
}

// ---------------- kernel 3: emission features ----------------
__global__ __launch_bounds__(256) void feats_kernel(const float* __restrict__ w_out,
                                                    const float* __restrict__ b_out) {
    const int lane = threadIdx.x & 31;
    const int warp = threadIdx.x >> 5;
    const int m = blockIdx.x * 8 + warp;
    const int t = m >> 6, b = m & 63;

    __shared__ float f_sm[8][16];

    float acc[16];
#pragma unroll
    for (int kk = 0; kk < 16; kk++) acc[kk] = 0.0f;

    const float* hf = g_hs + ((size_t)t * Bb + b) * Hh;
    const float* hb = g_hs + ((size_t)Tt * Bb * Hh) + ((size_t)t * Bb + b) * Hh;

#pragma unroll
    for (int i = 0; i < 16; i++) {
        int dd = i * 32 + lane;
        float hv = (dd < Hh) ? hf[dd] : hb[dd - Hh];
#pragma unroll
        for (int kk = 0; kk < 16; kk++) acc[kk] += hv * w_out[kk * HD + dd];
    }
#pragma unroll
    for (int kk = 0; kk < 16; kk++) {
        float s = acc[kk];
        s += __shfl_down_sync(0xffffffffu, s, 16);
        s += __shfl_down_sync(0xffffffffu, s, 8);
        s += __shfl_down_sync(0xffffffffu, s, 4);
        s += __shfl_down_sync(0xffffffffu, s, 2);
        s += __shfl_down_sync(0xffffffffu, s, 1);
        if (lane == 0) f_sm[warp][kk] = s;
    }
    __syncwarp();
    if (lane < 16)
        g_feats[((size_t)t * Bb + b) * Kk + lane] = f_sm[warp][lane] + b_out[lane];
}

// ---------------- kernel 4: Viterbi forward + backtrace ----------------
__global__ __launch_bounds__(32) void viterbi_kernel(const float* __restrict__ trans,
                                                     float* __restrict__ out) {
    const int b = blockIdx.x;
    const int lane = threadIdx.x;

    __shared__ unsigned char bp_sm[Tt][16];

    float trans_r[16];
#pragma unroll
    for (int p = 0; p < 16; p++)
        trans_r[p] = (lane < 16) ? trans[lane * 16 + p] : 0.0f;

    float fv = (lane == START_IDX) ? 0.0f : NEG;
    if (lane >= 16) fv = NEG;

    float feat_n = (lane < 16) ? g_feats[((size_t)0 * Bb + b) * Kk + lane] : 0.0f;

    for (int t = 0; t < Tt; t++) {
        float feat = feat_n;
        if (t + 1 < Tt)
            feat_n = (lane < 16) ? g_feats[((size_t)(t + 1) * Bb + b) * Kk + lane] : 0.0f;
        float m = -3.4e38f;
        int am = 0;
#pragma unroll
        for (int p = 0; p < 16; p++) {
            float v = __shfl_sync(0xffffffffu, fv, p) + trans_r[p];
            if (v > m) { m = v; am = p; }
        }
        float nfv = m + feat;
        fv = (lane < 16) ? nfv : NEG;
        if (lane < 16) bp_sm[t][lane] = (unsigned char)am;
    }
    __syncwarp();

    float best = -3.4e38f;
    int bt = 0;
#pragma unroll
    for (int s = 0; s < 16; s++) {
        float v = __shfl_sync(0xffffffffu, fv, s);
        float tv = v + trans[STOP_IDX * 16 + s];
        if (tv > best) { best = tv; bt = s; }
    }
    if (lane == 0) {
        out[b] = best;
        int tag = bt;
        for (int t = Tt - 1; t >= 0; t--) {
            out[64 + (size_t)t * Bb + b] = (float)tag;
            tag = bp_sm[t][tag];
        }
    }
}

// ---------------- launcher ----------------
extern "C" void kernel_launch(void* const* d_in, const int* in_sizes, int n_in,
                              void* d_out, int out_size) {
    const int*   sentence = (const int*)d_in[0];
    const float* emb      = (const float*)d_in[1];
    const float* w_ih_f   = (const float*)d_in[2];
    const float* w_hh_f   = (const float*)d_in[3];
    const float* b_f      = (const float*)d_in[4];
    const float* w_ih_b   = (const float*)d_in[5];
    const float* w_hh_b   = (const float*)d_in[6];
    const float* b_b      = (const float*)d_in[7];
    const float* w_out    = (const float*)d_in[8];
    const float* b_out    = (const float*)d_in[9];
    const float* trans    = (const float*)d_in[10];
    float* out = (float*)d_out;
    (void)in_sizes; (void)n_in; (void)out_size;

    prep_whh_kernel<<<2048, 256>>>(w_hh_f, w_hh_b);
    dim3 pg(G4H / 128, (Tt * Bb) / 128, 2);
    input_proj_kernel<<<pg, 256>>>(sentence, emb, w_ih_f, b_f, w_ih_b, b_b);
    lstm_rec_kernel<<<128, 256>>>();
    feats_kernel<<<(Tt * Bb) / 8, 256>>>(w_out, b_out);
    viterbi_kernel<<<Bb, 32>>>(trans, out);
}

// round 5
// speedup vs baseline: 3.8065x; 1.0781x over previous
#include <cuda_runtime.h>
#include <cuda_bf16.h>
#include <math.h>
#include <stdint.h>

// Problem constants
#define Vv 50000
#define Ee 256
#define HD 512
#define Hh 256
#define Bb 64
#define Tt 512
#define Kk 16
#define G4H 1024
#define START_IDX 14
#define STOP_IDX 15
#define NEG (-10000.0f)

// ---------------- device scratch ----------------
__device__ __align__(16) float g_Wr2[2 * 1024 * 256];               // [d][col][k], col=j*4+gate
__device__ __align__(16) float g_Gpre[2ull * Tt * Bb * G4H];        // 268 MB
__device__ __align__(16) float g_hs[2ull * Tt * Bb * Hh];           // 67 MB
__device__ float g_feats[(size_t)Tt * Bb * Kk];

// ---------------- f32x2 helpers ----------------
__device__ __forceinline__ void ffma2(unsigned long long& d,
                                      unsigned long long a, unsigned long long b) {
    asm("fma.rn.f32x2 %0, %1, %2, %0;" : "+l"(d) : "l"(a), "l"(b));
}
__device__ __forceinline__ unsigned long long pack2(float x, float y) {
    unsigned long long r;
    asm("mov.b64 %0, {%1, %2};" : "=l"(r) : "f"(x), "f"(y));
    return r;
}
__device__ __forceinline__ float hadd2(unsigned long long v) {
    float lo = __uint_as_float((unsigned)(v & 0xffffffffull));
    float hi = __uint_as_float((unsigned)(v >> 32));
    return lo + hi;
}
__device__ __forceinline__ float fsig(float x) {
    return __fdividef(1.0f, 1.0f + __expf(-x));
}
__device__ __forceinline__ float ftanh(float x) {
    return __fdividef(2.0f, 1.0f + __expf(-2.0f * x)) - 1.0f;
}

// ---------------- cluster mbarrier helpers ----------------
__device__ __forceinline__ uint32_t smem_u32_of(const void* p) {
    uint32_t a;
    asm("{ .reg .u64 t0; cvta.to.shared.u64 t0, %1; cvt.u32.u64 %0, t0; }"
        : "=r"(a) : "l"(p));
    return a;
}
__device__ __forceinline__ void mbar_init(uint32_t mbar, uint32_t cnt) {
    asm volatile("mbarrier.init.shared.b64 [%0], %1;" :: "r"(mbar), "r"(cnt) : "memory");
}
__device__ __forceinline__ void mbar_arrive_expect(uint32_t mbar, uint32_t tx) {
    asm volatile("mbarrier.arrive.expect_tx.shared.b64 _, [%0], %1;"
                 :: "r"(mbar), "r"(tx) : "memory");
}
__device__ __forceinline__ void mbar_wait_cluster(uint32_t mbar, uint32_t parity) {
    asm volatile(
        "{\n\t"
        ".reg .pred P1;\n\t"
        "WAIT_%=:\n\t"
        "mbarrier.try_wait.parity.acquire.cluster.shared::cta.b64 P1, [%0], %1, 0x989680;\n\t"
        "@P1 bra.uni DONE_%=;\n\t"
        "bra.uni WAIT_%=;\n\t"
        "DONE_%=:\n\t"
        "}"
        :: "r"(mbar), "r"(parity) : "memory");
}
__device__ __forceinline__ uint32_t mapa_u32(uint32_t addr, uint32_t rank) {
    uint32_t r;
    asm("mapa.shared::cluster.u32 %0, %1, %2;" : "=r"(r) : "r"(addr), "r"(rank));
    return r;
}
__device__ __forceinline__ void st_async_f64(uint32_t daddr, unsigned long long val,
                                             uint32_t mbar) {
    asm volatile(
        "st.async.weak.shared::cluster.mbarrier::complete_tx::bytes.b64 [%0], %1, [%2];"
        :: "r"(daddr), "l"(val), "r"(mbar) : "memory");
}

// ---------------- kernel 0: reorder recurrent weights ----------------
__global__ void prep_whh_kernel(const float* __restrict__ whh_f,
                                const float* __restrict__ whh_b) {
    int idx = blockIdx.x * blockDim.x + threadIdx.x;   // over 2*1024*256
    int k = idx & 255;
    int col = (idx >> 8) & 1023;
    int d = idx >> 18;
    int gate = col & 3;
    int j = col >> 2;
    const float* w = d ? whh_b : whh_f;
    g_Wr2[idx] = w[(gate * 256 + j) * 256 + k];
}

// ---------------- kernel 1: embedding gather + input projection SGEMM ----------------
// Block tile 256m x 128n, BK=8, thread tile 16m x 8n.
// A natural layout -> LDS.128 yields native (m,m+1) pairs for FFMA2.
// B duplicated in registers via pack2 (8 MOVs/kk, hidden in alu pipe).
// 0.75 B/MAC LDS ratio; A reads broadcast 16-wide -> LDS far under fma floor.
__global__ __launch_bounds__(256, 1) void input_proj_kernel(
    const int*   __restrict__ sentence,
    const float* __restrict__ emb,
    const float* __restrict__ wih_f, const float* __restrict__ bf,
    const float* __restrict__ wih_b, const float* __restrict__ bbias) {
    const int d = blockIdx.z;
    const float* wih = d ? wih_b : wih_f;
    const float* bias = d ? bbias : bf;

    __shared__ __align__(16) float As[2][8][256];    // 16 KB
    __shared__ __align__(16) float Bs[2][8][128];    // 8 KB

    const int tid = threadIdx.x;
    const int tx = tid & 15;          // n-group
    const int ty = tid >> 4;          // m-group
    const int m0 = blockIdx.y * 256;
    const int c0 = blockIdx.x * 128;

    // A loader: one m-row per thread
    const int mA = m0 + tid;
    const int tok = sentence[(mA & 63) * Tt + (mA >> 6)];
    const float* arow = emb + (size_t)tok * Ee;
    // B loader: row tid>>1, k-offset (tid&1)*4
    const int cB = c0 + (tid >> 1);
    const int rB = ((cB & 3) << 8) | (cB >> 2);
    const float* brow = wih + (size_t)rB * Ee + (tid & 1) * 4;

    unsigned long long acc2[8][8];
#pragma unroll
    for (int i = 0; i < 8; i++)
#pragma unroll
        for (int j = 0; j < 8; j++) acc2[i][j] = 0ull;

    // prologue: fill buffer 0
    {
        float4 a0 = *(const float4*)(arow + 0);
        float4 a1 = *(const float4*)(arow + 4);
        float4 bv = *(const float4*)(brow);
        float av[8] = {a0.x, a0.y, a0.z, a0.w, a1.x, a1.y, a1.z, a1.w};
#pragma unroll
        for (int i = 0; i < 8; i++) As[0][i][tid] = av[i];
        float bvv[4] = {bv.x, bv.y, bv.z, bv.w};
#pragma unroll
        for (int i = 0; i < 4; i++) Bs[0][(tid & 1) * 4 + i][tid >> 1] = bvv[i];
    }
    __syncthreads();

    for (int it = 0; it < 32; it++) {
        const int cur = it & 1;
        float4 a0n, a1n, bvn;
        if (it < 31) {
            a0n = *(const float4*)(arow + (it + 1) * 8);
            a1n = *(const float4*)(arow + (it + 1) * 8 + 4);
            bvn = *(const float4*)(brow + (it + 1) * 8);
        }
#pragma unroll
        for (int kk = 0; kk < 8; kk++) {
            const ulonglong2* pa = (const ulonglong2*)&As[cur][kk][ty * 16];
            ulonglong2 p0 = pa[0], p1 = pa[1], p2 = pa[2], p3 = pa[3];
            unsigned long long ra[8] = {p0.x, p0.y, p1.x, p1.y,
                                        p2.x, p2.y, p3.x, p3.y};
            const float4* pb = (const float4*)&Bs[cur][kk][tx * 8];
            float4 b0 = pb[0], b1 = pb[1];
            unsigned long long rb2[8];
            rb2[0] = pack2(b0.x, b0.x); rb2[1] = pack2(b0.y, b0.y);
            rb2[2] = pack2(b0.z, b0.z); rb2[3] = pack2(b0.w, b0.w);
            rb2[4] = pack2(b1.x, b1.x); rb2[5] = pack2(b1.y, b1.y);
            rb2[6] = pack2(b1.z, b1.z); rb2[7] = pack2(b1.w, b1.w);
#pragma unroll
            for (int mp = 0; mp < 8; mp++)
#pragma unroll
                for (int n = 0; n < 8; n++) ffma2(acc2[mp][n], ra[mp], rb2[n]);
        }
        if (it < 31) {
            const int nxt = cur ^ 1;
            float av[8] = {a0n.x, a0n.y, a0n.z, a0n.w, a1n.x, a1n.y, a1n.z, a1n.w};
#pragma unroll
            for (int i = 0; i < 8; i++) As[nxt][i][tid] = av[i];
            float bvv[4] = {bvn.x, bvn.y, bvn.z, bvn.w};
#pragma unroll
            for (int i = 0; i < 4; i++) Bs[nxt][(tid & 1) * 4 + i][tid >> 1] = bvv[i];
        }
        __syncthreads();
    }

    float bsv[8];
#pragma unroll
    for (int n = 0; n < 8; n++) {
        int c = c0 + tx * 8 + n;
        bsv[n] = bias[((c & 3) << 8) | (c >> 2)];
    }
#pragma unroll
    for (int mp = 0; mp < 8; mp++) {
        const int me = m0 + ty * 16 + 2 * mp;      // even m
        float oe[8], oo[8];
#pragma unroll
        for (int n = 0; n < 8; n++) {
            unsigned long long v = acc2[mp][n];
            oe[n] = __uint_as_float((unsigned)(v & 0xffffffffull)) + bsv[n];
            oo[n] = __uint_as_float((unsigned)(v >> 32)) + bsv[n];
        }
        {
            int t = me >> 6, b = me & 63;
            float* outp = g_Gpre + (((size_t)d * Tt + t) * Bb + b) * G4H + c0 + tx * 8;
            *(float4*)(outp) = make_float4(oe[0], oe[1], oe[2], oe[3]);
            *(float4*)(outp + 4) = make_float4(oe[4], oe[5], oe[6], oe[7]);
        }
        {
            int mo = me + 1;
            int t = mo >> 6, b = mo & 63;
            float* outp = g_Gpre + (((size_t)d * Tt + t) * Bb + b) * G4H + c0 + tx * 8;
            *(float4*)(outp) = make_float4(oo[0], oo[1], oo[2], oo[3]);
            *(float4*)(outp + 4) = make_float4(oo[4], oo[5], oo[6], oo[7]);
        }
    }
}

// ---------------- kernel 2: LSTM recurrence (cluster, mbarrier/st.async sync) ----
// 128 CTAs, cluster 8. cid=blk>>3: d=cid>>3, batch group bg=cid&7 (8 batches).
// CTA rank r owns j in [r*32, r*32+32). Thread: jl=t>>3, kq=t&7 (k-split 8-way).
// Weights in 128 registers. h pair-packed (shfl_xor 8) and broadcast via
// st.async.b64 from even-jl threads; per-step sync = tx-counted mbarrier.
__global__ void __cluster_dims__(8, 1, 1) __launch_bounds__(256, 1) lstm_rec_kernel() {
    const int tidx = threadIdx.x;
    const int kq = tidx & 7;
    const int jl = tidx >> 3;
    const int cid = blockIdx.x >> 3;
    const int r = blockIdx.x & 7;
    const int d = cid >> 3;
    const int bg = cid & 7;
    const int b = bg * 8 + kq;
    const int jglob = r * 32 + jl;
    const int col0 = jglob * 4;

    __shared__ __align__(16) float h_sm[2][8][260];
    __shared__ __align__(8) unsigned long long mbars[2];

    // ---- weights into registers ----
    unsigned long long wu[4][16];
    const float* wbase = g_Wr2 + (size_t)d * 1024 * 256;
#pragma unroll
    for (int g = 0; g < 4; g++) {
        const ulonglong2* p = (const ulonglong2*)(wbase + (size_t)(col0 + g) * 256 + kq * 32);
#pragma unroll
        for (int q = 0; q < 8; q++) {
            ulonglong2 v = p[q];
            wu[g][2 * q + 0] = v.x;
            wu[g][2 * q + 1] = v.y;
        }
    }

    // zero step-0 buffer
    for (int i = tidx; i < 8 * 260; i += 256) ((float*)h_sm[0])[i] = 0.0f;
    float c = 0.0f;

    const uint32_t h_base = smem_u32_of(h_sm);
    const uint32_t mb_base = smem_u32_of(mbars);
    const uint32_t dmb = mb_base - h_base;

    if (tidx == 0) {
        mbar_init(mb_base, 1);
        mbar_init(mb_base + 8, 1);
        mbar_arrive_expect(mb_base, 8192);
        mbar_arrive_expect(mb_base + 8, 8192);
    }
    __syncthreads();
    asm volatile("barrier.cluster.arrive.aligned;" ::: "memory");
    asm volatile("barrier.cluster.wait.aligned;" ::: "memory");

    uint32_t ph[8];
#pragma unroll
    for (int rk = 0; rk < 8; rk++) ph[rk] = mapa_u32(h_base, rk);

    // pair store: even-jl thread writes (h_j, h_{j+1}) at float offset kq*260 + jglob
    const uint32_t hoff0 = (uint32_t)((kq * 260 + jglob) * 4);
    const uint32_t hoff1 = (uint32_t)(8 * 260 * 4) + hoff0;
    const bool sender = ((jl & 1) == 0);

    const int t0 = d ? (Tt - 1) : 0;
    const int tstep = d ? -1 : 1;
    const float4* gpre4 = (const float4*)g_Gpre;

    float4 g4 = gpre4[(((size_t)d * Tt + t0) * Bb + b) * 256 + jglob];

    for (int s = 0; s < Tt; s++) {
        const int t = t0 + s * tstep;
        const int cur = s & 1;

        if (s > 0) {
            uint32_t mb = mb_base + (uint32_t)(cur * 8);
            mbar_wait_cluster(mb, ((s - 1) >> 1) & 1);
            if (tidx == 0) mbar_arrive_expect(mb, 8192);   // re-arm for step s+2
        }

        // ---- GEMM: accf[g][slot], row = slot ^ kq ----
        float accf[4][8];
#pragma unroll
        for (int sl = 0; sl < 8; sl++) {
            unsigned long long a2[4] = {0ull, 0ull, 0ull, 0ull};
            const ulonglong2* hp = (const ulonglong2*)&h_sm[cur][sl ^ kq][kq * 32];
#pragma unroll
            for (int i = 0; i < 8; i++) {
                ulonglong2 h4 = hp[i];
                ffma2(a2[0], wu[0][2 * i], h4.x); ffma2(a2[0], wu[0][2 * i + 1], h4.y);
                ffma2(a2[1], wu[1][2 * i], h4.x); ffma2(a2[1], wu[1][2 * i + 1], h4.y);
                ffma2(a2[2], wu[2][2 * i], h4.x); ffma2(a2[2], wu[2][2 * i + 1], h4.y);
                ffma2(a2[3], wu[3][2 * i], h4.x); ffma2(a2[3], wu[3][2 * i + 1], h4.y);
            }
#pragma unroll
            for (int g = 0; g < 4; g++) accf[g][sl] = hadd2(a2[g]);
        }

        // prefetch next step's Gpre
        float4 g4n = g4;
        if (s + 1 < Tt) {
            const int tn = t + tstep;
            g4n = gpre4[(((size_t)d * Tt + tn) * Bb + b) * 256 + jglob];
        }

        // ---- reduce-scatter over kq lanes ----
#pragma unroll
        for (int g = 0; g < 4; g++) {
            accf[g][0] += __shfl_xor_sync(0xffffffffu, accf[g][4], 4);
            accf[g][1] += __shfl_xor_sync(0xffffffffu, accf[g][5], 4);
            accf[g][2] += __shfl_xor_sync(0xffffffffu, accf[g][6], 4);
            accf[g][3] += __shfl_xor_sync(0xffffffffu, accf[g][7], 4);
            accf[g][0] += __shfl_xor_sync(0xffffffffu, accf[g][2], 2);
            accf[g][1] += __shfl_xor_sync(0xffffffffu, accf[g][3], 2);
            accf[g][0] += __shfl_xor_sync(0xffffffffu, accf[g][1], 1);
        }

        // ---- LSTM cell ----
        float a0 = accf[0][0] + g4.x;
        float a1 = accf[1][0] + g4.y;
        float a2v = accf[2][0] + g4.z;
        float a3 = accf[3][0] + g4.w;
        float ig = fsig(a0), fg = fsig(a1), gv = ftanh(a2v), og = fsig(a3);
        c = fg * c + ig * gv;
        float h = og * ftanh(c);

        g_hs[(((size_t)d * Tt + t) * Bb + b) * Hh + jglob] = h;

        // pair h with jl-neighbor (lane ^ 8), even-jl threads send b64
        float hN = __shfl_xor_sync(0xffffffffu, h, 8);
        if (s + 1 < Tt && sender) {
            unsigned long long hv = pack2(h, hN);
            const uint32_t doff = (cur ^ 1) ? hoff1 : hoff0;
            const uint32_t moff = dmb + (uint32_t)((cur ^ 1) * 8);
#pragma unroll
            for (int rk = 0; rk < 8; rk++)
                st_async_f64(ph[rk] + doff, hv, ph[rk] + moff);
        }
        g4 = g4n;
    }
}

// ---------------- kernel 3: emission features ----------------
__global__ __launch_bounds__(256) void feats_kernel(const float* __restrict__ w_out,
                                                    const float* __restrict__ b_out) {
    const int lane = threadIdx.x & 31;
    const int warp = threadIdx.x >> 5;
    const int m = blockIdx.x * 8 + warp;
    const int t = m >> 6, b = m & 63;

    __shared__ float f_sm[8][16];

    float acc[16];
#pragma unroll
    for (int kk = 0; kk < 16; kk++) acc[kk] = 0.0f;

    const float* hf = g_hs + ((size_t)t * Bb + b) * Hh;
    const float* hb = g_hs + ((size_t)Tt * Bb * Hh) + ((size_t)t * Bb + b) * Hh;

#pragma unroll
    for (int i = 0; i < 16; i++) {
        int dd = i * 32 + lane;
        float hv = (dd < Hh) ? hf[dd] : hb[dd - Hh];
#pragma unroll
        for (int kk = 0; kk < 16; kk++) acc[kk] += hv * w_out[kk * HD + dd];
    }
#pragma unroll
    for (int kk = 0; kk < 16; kk++) {
        float s = acc[kk];
        s += __shfl_down_sync(0xffffffffu, s, 16);
        s += __shfl_down_sync(0xffffffffu, s, 8);
        s += __shfl_down_sync(0xffffffffu, s, 4);
        s += __shfl_down_sync(0xffffffffu, s, 2);
        s += __shfl_down_sync(0xffffffffu, s, 1);
        if (lane == 0) f_sm[warp][kk] = s;
    }
    __syncwarp();
    if (lane < 16)
        g_feats[((size_t)t * Bb + b) * Kk + lane] = f_sm[warp][lane] + b_out[lane];
}

// ---------------- kernel 4: Viterbi forward + backtrace ----------------
__global__ __launch_bounds__(32) void viterbi_kernel(const float* __restrict__ trans,
                                                     float* __restrict__ out) {
    const int b = blockIdx.x;
    const int lane = threadIdx.x;

    __shared__ unsigned char bp_sm[Tt][16];

    float trans_r[16];
#pragma unroll
    for (int p = 0; p < 16; p++)
        trans_r[p] = (lane < 16) ? trans[lane * 16 + p] : 0.0f;

    float fv = (lane == START_IDX) ? 0.0f : NEG;
    if (lane >= 16) fv = NEG;

    float feat_n = (lane < 16) ? g_feats[((size_t)0 * Bb + b) * Kk + lane] : 0.0f;

    for (int t = 0; t < Tt; t++) {
        float feat = feat_n;
        if (t + 1 < Tt)
            feat_n = (lane < 16) ? g_feats[((size_t)(t + 1) * Bb + b) * Kk + lane] : 0.0f;
        float m = -3.4e38f;
        int am = 0;
#pragma unroll
        for (int p = 0; p < 16; p++) {
            float v = __shfl_sync(0xffffffffu, fv, p) + trans_r[p];
            if (v > m) { m = v; am = p; }
        }
        float nfv = m + feat;
        fv = (lane < 16) ? nfv : NEG;
        if (lane < 16) bp_sm[t][lane] = (unsigned char)am;
    }
    __syncwarp();

    float best = -3.4e38f;
    int bt = 0;
#pragma unroll
    for (int s = 0; s < 16; s++) {
        float v = __shfl_sync(0xffffffffu, fv, s);
        float tv = v + trans[STOP_IDX * 16 + s];
        if (tv > best) { best = tv; bt = s; }
    }
    if (lane == 0) {
        out[b] = best;
        int tag = bt;
        for (int t = Tt - 1; t >= 0; t--) {
            out[64 + (size_t)t * Bb + b] = (float)tag;
            tag = bp_sm[t][tag];
        }
    }
}

// ---------------- launcher ----------------
extern "C" void kernel_launch(void* const* d_in, const int* in_sizes, int n_in,
                              void* d_out, int out_size) {
    const int*   sentence = (const int*)d_in[0];
    const float* emb      = (const float*)d_in[1];
    const float* w_ih_f   = (const float*)d_in[2];
    const float* w_hh_f   = (const float*)d_in[3];
    const float* b_f      = (const float*)d_in[4];
    const float* w_ih_b   = (const float*)d_in[5];
    const float* w_hh_b   = (const float*)d_in[6];
    const float* b_b      = (const float*)d_in[7];
    const float* w_out    = (const float*)d_in[8];
    const float* b_out    = (const float*)d_in[9];
    const float* trans    = (const float*)d_in[10];
    float* out = (float*)d_out;
    (void)in_sizes; (void)n_in; (void)out_size;

    prep_whh_kernel<<<2048, 256>>>(w_hh_f, w_hh_b);
    dim3 pg(G4H / 128, (Tt * Bb) / 256, 2);
    input_proj_kernel<<<pg, 256>>>(sentence, emb, w_ih_f, b_f, w_ih_b, b_b);
    lstm_rec_kernel<<<128, 256>>>();
    feats_kernel<<<(Tt * Bb) / 8, 256>>>(w_out, b_out);
    viterbi_kernel<<<Bb, 32>>>(trans, out);
}